// round 2
// baseline (speedup 1.0000x reference)
#include <cuda_runtime.h>
#include <cuda_bf16.h>
#include <math.h>

// Problem constants
#define BQ 8
#define LQ 1024
#define DM 1024
#define NH 16
#define DK 64
#define BL (BQ * LQ)          // 8192 rows
#define ATTN_ELEMS (128ull * 1024ull * 1024ull)
#define OUT_ELEMS  (8ull * 1024ull * 1024ull)

// Scratch (device globals: allocation-free rule)
__device__ float g_qs[BL * DM];
__device__ float g_ks[BL * DM];
__device__ float g_vs[BL * DM];
__device__ float g_oh[BL * DM];
__device__ float g_x [BL * DM];

// ---------------------------------------------------------------------------
// GEMM for QKV projection: C[m, h*64+k] = sum_d A[m,d] * W[h, d, k]
// A: [8192,1024] row-major.  W: [16,1024,64].  C: [8192,1024].
// 128x128 block tile, BK=8, 256 threads, 8x8 per thread.
// ---------------------------------------------------------------------------
__global__ __launch_bounds__(256) void gemm_qkv(const float* __restrict__ A,
                                                const float* __restrict__ W,
                                                float* __restrict__ C)
{
    __shared__ float As[8][128];
    __shared__ float Bs[8][128];
    const int n0 = blockIdx.x * 128;
    const int m0 = blockIdx.y * 128;
    const int tid = threadIdx.x;

    const int ar = tid >> 1;           // 0..127 (row within A tile)
    const int ac = (tid & 1) * 4;      // 0 or 4 (k-col group)
    const int bd = tid >> 5;           // 0..7   (k-row of B tile)
    const int bc = (tid & 31) * 4;     // 0..124 (n-col group)
    const int r0 = (tid >> 4) * 8;
    const int c0 = (tid & 15) * 8;

    float acc[8][8];
    #pragma unroll
    for (int i = 0; i < 8; i++)
        #pragma unroll
        for (int j = 0; j < 8; j++) acc[i][j] = 0.f;

    for (int k0 = 0; k0 < DM; k0 += 8) {
        float4 av = *(const float4*)&A[(size_t)(m0 + ar) * DM + k0 + ac];
        As[ac + 0][ar] = av.x;
        As[ac + 1][ar] = av.y;
        As[ac + 2][ar] = av.z;
        As[ac + 3][ar] = av.w;
        {
            int c = n0 + bc;
            // W element (d = k0+bd, col c): h = c>>6, kk = c&63
            const float* wp = &W[(size_t)((c >> 6) * DM + (k0 + bd)) * 64 + (c & 63)];
            *(float4*)&Bs[bd][bc] = *(const float4*)wp;
        }
        __syncthreads();
        #pragma unroll
        for (int kk = 0; kk < 8; kk++) {
            float a[8], b[8];
            *(float4*)(a)     = *(const float4*)&As[kk][r0];
            *(float4*)(a + 4) = *(const float4*)&As[kk][r0 + 4];
            *(float4*)(b)     = *(const float4*)&Bs[kk][c0];
            *(float4*)(b + 4) = *(const float4*)&Bs[kk][c0 + 4];
            #pragma unroll
            for (int i = 0; i < 8; i++)
                #pragma unroll
                for (int j = 0; j < 8; j++)
                    acc[i][j] += a[i] * b[j];
        }
        __syncthreads();
    }
    #pragma unroll
    for (int i = 0; i < 8; i++) {
        #pragma unroll
        for (int j = 0; j < 8; j += 4) {
            *(float4*)&C[(size_t)(m0 + r0 + i) * DM + n0 + c0 + j] = *(float4*)&acc[i][j];
        }
    }
}

// ---------------------------------------------------------------------------
// Output projection: C[m,n] = sum_c A[m,c]*Wp[n,c] + bias[n] + resid[m,n]
// Wp: [1024,1024] row-major, used transposed.
// ---------------------------------------------------------------------------
__global__ __launch_bounds__(256) void gemm_proj(const float* __restrict__ A,
                                                 const float* __restrict__ Wp,
                                                 const float* __restrict__ bias,
                                                 const float* __restrict__ resid,
                                                 float* __restrict__ C)
{
    __shared__ float As[8][128];
    __shared__ float Bs[8][128];
    const int n0 = blockIdx.x * 128;
    const int m0 = blockIdx.y * 128;
    const int tid = threadIdx.x;

    const int ar = tid >> 1;
    const int ac = (tid & 1) * 4;
    const int r0 = (tid >> 4) * 8;
    const int c0 = (tid & 15) * 8;

    float acc[8][8];
    #pragma unroll
    for (int i = 0; i < 8; i++)
        #pragma unroll
        for (int j = 0; j < 8; j++) acc[i][j] = 0.f;

    for (int k0 = 0; k0 < DM; k0 += 8) {
        float4 av = *(const float4*)&A[(size_t)(m0 + ar) * DM + k0 + ac];
        As[ac + 0][ar] = av.x;
        As[ac + 1][ar] = av.y;
        As[ac + 2][ar] = av.z;
        As[ac + 3][ar] = av.w;
        // B tile: Bs[d][c] = Wp[(n0+c)*1024 + k0+d] — threads walk d fastest
        #pragma unroll
        for (int t = 0; t < 4; t++) {
            int idx = tid + t * 256;       // 0..1023
            int d = idx & 7;
            int c = idx >> 3;
            Bs[d][c] = Wp[(size_t)(n0 + c) * DM + k0 + d];
        }
        __syncthreads();
        #pragma unroll
        for (int kk = 0; kk < 8; kk++) {
            float a[8], b[8];
            *(float4*)(a)     = *(const float4*)&As[kk][r0];
            *(float4*)(a + 4) = *(const float4*)&As[kk][r0 + 4];
            *(float4*)(b)     = *(const float4*)&Bs[kk][c0];
            *(float4*)(b + 4) = *(const float4*)&Bs[kk][c0 + 4];
            #pragma unroll
            for (int i = 0; i < 8; i++)
                #pragma unroll
                for (int j = 0; j < 8; j++)
                    acc[i][j] += a[i] * b[j];
        }
        __syncthreads();
    }
    #pragma unroll
    for (int i = 0; i < 8; i++) {
        int m = m0 + r0 + i;
        #pragma unroll
        for (int j = 0; j < 8; j++) {
            int n = n0 + c0 + j;
            C[(size_t)m * DM + n] = acc[i][j] + bias[n] + resid[(size_t)m * DM + n];
        }
    }
}

// ---------------------------------------------------------------------------
// Scores: S[hb, i, j] = (Q_s[h,b,i,:] . K_s[h,b,j,:]) / 32, mask -> -inf
// One block = 64x64 tile of one (h,b). K=64 fully in smem.
// ---------------------------------------------------------------------------
__global__ __launch_bounds__(256) void scores_kernel(const float* __restrict__ Qs,
                                                     const float* __restrict__ Ks,
                                                     const unsigned char* __restrict__ mask,
                                                     float* __restrict__ attns)
{
    __shared__ float Qt[64][64];   // [d][i]
    __shared__ float Kt[64][64];   // [d][j]
    const int j0 = blockIdx.x * 64;
    const int i0 = blockIdx.y * 64;
    const int hb = blockIdx.z;             // h*8 + b
    const int h = hb >> 3;
    const int b = hb & 7;
    const int tid = threadIdx.x;
    const int base = b * LQ;
    const int hc = h * DK;

    {
        int r = tid >> 2;             // 0..63
        int cg = (tid & 3) * 16;      // 0,16,32,48
        #pragma unroll
        for (int s = 0; s < 4; s++) {
            int c = cg + s * 4;
            float4 vq = *(const float4*)&Qs[(size_t)(base + i0 + r) * DM + hc + c];
            Qt[c + 0][r] = vq.x; Qt[c + 1][r] = vq.y; Qt[c + 2][r] = vq.z; Qt[c + 3][r] = vq.w;
            float4 vk = *(const float4*)&Ks[(size_t)(base + j0 + r) * DM + hc + c];
            Kt[c + 0][r] = vk.x; Kt[c + 1][r] = vk.y; Kt[c + 2][r] = vk.z; Kt[c + 3][r] = vk.w;
        }
    }
    __syncthreads();

    float acc[4][4];
    #pragma unroll
    for (int i = 0; i < 4; i++)
        #pragma unroll
        for (int j = 0; j < 4; j++) acc[i][j] = 0.f;

    const int ti = (tid >> 4) * 4;
    const int tj = (tid & 15) * 4;
    #pragma unroll 8
    for (int d = 0; d < 64; d++) {
        float4 a = *(const float4*)&Qt[d][ti];
        float4 c = *(const float4*)&Kt[d][tj];
        float av[4] = {a.x, a.y, a.z, a.w};
        float bv[4] = {c.x, c.y, c.z, c.w};
        #pragma unroll
        for (int i = 0; i < 4; i++)
            #pragma unroll
            for (int j = 0; j < 4; j++)
                acc[i][j] += av[i] * bv[j];
    }

    const float scale = 0.03125f;   // 1/sqrt(1024)
    #pragma unroll
    for (int i = 0; i < 4; i++) {
        int gi = i0 + ti + i;
        const unsigned char* mrow = &mask[((size_t)b * LQ + gi) * LQ + j0 + tj];
        float* orow = &attns[((size_t)hb * LQ + gi) * LQ + j0 + tj];
        #pragma unroll
        for (int j = 0; j < 4; j++) {
            float s = acc[i][j] * scale;
            if (mrow[j]) s = -INFINITY;
            orow[j] = s;
        }
    }
}

// ---------------------------------------------------------------------------
// Row softmax, in place. One block per row of 1024.
// ---------------------------------------------------------------------------
__global__ __launch_bounds__(256) void softmax_kernel(float* __restrict__ attns)
{
    __shared__ float sred[32];
    float* p = attns + (size_t)blockIdx.x * 1024;
    const int tid = threadIdx.x;

    float4 v = *(const float4*)&p[tid * 4];
    float m = fmaxf(fmaxf(v.x, v.y), fmaxf(v.z, v.w));
    #pragma unroll
    for (int o = 16; o; o >>= 1) m = fmaxf(m, __shfl_xor_sync(0xffffffffu, m, o));
    if ((tid & 31) == 0) sred[tid >> 5] = m;
    __syncthreads();
    if (tid == 0) {
        float t = sred[0];
        #pragma unroll
        for (int i = 1; i < 8; i++) t = fmaxf(t, sred[i]);
        sred[8] = t;
    }
    __syncthreads();
    const float bmax = sred[8];

    float e0 = expf(v.x - bmax), e1 = expf(v.y - bmax);
    float e2 = expf(v.z - bmax), e3 = expf(v.w - bmax);
    float s = e0 + e1 + e2 + e3;
    #pragma unroll
    for (int o = 16; o; o >>= 1) s += __shfl_xor_sync(0xffffffffu, s, o);
    if ((tid & 31) == 0) sred[16 + (tid >> 5)] = s;
    __syncthreads();
    if (tid == 0) {
        float t = 0.f;
        #pragma unroll
        for (int i = 0; i < 8; i++) t += sred[16 + i];
        sred[24] = t;
    }
    __syncthreads();
    const float inv = 1.0f / sred[24];
    float4 o4 = make_float4(e0 * inv, e1 * inv, e2 * inv, e3 * inv);
    *(float4*)&p[tid * 4] = o4;
}

// ---------------------------------------------------------------------------
// AV: Oh[b, i, h*64+v] = sum_j attn[hb, i, j] * Vs[b, j, h*64+v]
// One block = 64 rows x full head (64 cols) of one (h,b).
// ---------------------------------------------------------------------------
__global__ __launch_bounds__(256) void av_kernel(const float* __restrict__ attns,
                                                 const float* __restrict__ Vs,
                                                 float* __restrict__ Oh)
{
    __shared__ float At[32][64];  // [j][i]
    __shared__ float Bs[32][64];  // [j][v]
    const int i0 = blockIdx.x * 64;
    const int hb = blockIdx.y;
    const int h = hb >> 3;
    const int b = hb & 7;
    const int tid = threadIdx.x;
    const float* arow = attns + (size_t)hb * LQ * LQ;
    const int hc = h * DK;

    float acc[4][4];
    #pragma unroll
    for (int i = 0; i < 4; i++)
        #pragma unroll
        for (int j = 0; j < 4; j++) acc[i][j] = 0.f;

    const int ti = (tid >> 4) * 4;
    const int tv = (tid & 15) * 4;

    for (int j0 = 0; j0 < LQ; j0 += 32) {
        {   // A tile: 64 rows x 32 j
            int r = tid >> 2;          // 0..63
            int c = (tid & 3) * 8;     // 0,8,16,24
            float4 x = *(const float4*)&arow[(size_t)(i0 + r) * LQ + j0 + c];
            float4 y = *(const float4*)&arow[(size_t)(i0 + r) * LQ + j0 + c + 4];
            At[c + 0][r] = x.x; At[c + 1][r] = x.y; At[c + 2][r] = x.z; At[c + 3][r] = x.w;
            At[c + 4][r] = y.x; At[c + 5][r] = y.y; At[c + 6][r] = y.z; At[c + 7][r] = y.w;
        }
        {   // B tile: 32 j x 64 v
            int r = tid >> 3;          // 0..31
            int c = (tid & 7) * 8;     // 0..56
            const float* vp = &Vs[((size_t)b * LQ + j0 + r) * DM + hc + c];
            *(float4*)&Bs[r][c]     = *(const float4*)vp;
            *(float4*)&Bs[r][c + 4] = *(const float4*)(vp + 4);
        }
        __syncthreads();
        #pragma unroll 8
        for (int jj = 0; jj < 32; jj++) {
            float4 a = *(const float4*)&At[jj][ti];
            float4 c = *(const float4*)&Bs[jj][tv];
            float av[4] = {a.x, a.y, a.z, a.w};
            float bv[4] = {c.x, c.y, c.z, c.w};
            #pragma unroll
            for (int i = 0; i < 4; i++)
                #pragma unroll
                for (int j = 0; j < 4; j++)
                    acc[i][j] += av[i] * bv[j];
        }
        __syncthreads();
    }
    #pragma unroll
    for (int i = 0; i < 4; i++) {
        float* op = &Oh[((size_t)b * LQ + i0 + ti + i) * DM + hc + tv];
        *(float4*)op = *(float4*)&acc[i][0];
    }
}

// ---------------------------------------------------------------------------
// LayerNorm: one block per row of 1024.
// ---------------------------------------------------------------------------
__global__ __launch_bounds__(256) void ln_kernel(const float* __restrict__ X,
                                                 const float* __restrict__ gamma,
                                                 const float* __restrict__ beta,
                                                 float* __restrict__ out)
{
    __shared__ float sred[32];
    const float* p = X + (size_t)blockIdx.x * DM;
    const int tid = threadIdx.x;

    float4 v = *(const float4*)&p[tid * 4];
    float s  = v.x + v.y + v.z + v.w;
    float sq = v.x * v.x + v.y * v.y + v.z * v.z + v.w * v.w;
    #pragma unroll
    for (int o = 16; o; o >>= 1) {
        s  += __shfl_xor_sync(0xffffffffu, s,  o);
        sq += __shfl_xor_sync(0xffffffffu, sq, o);
    }
    if ((tid & 31) == 0) { sred[tid >> 5] = s; sred[8 + (tid >> 5)] = sq; }
    __syncthreads();
    if (tid == 0) {
        float ts = 0.f, tq = 0.f;
        #pragma unroll
        for (int i = 0; i < 8; i++) { ts += sred[i]; tq += sred[8 + i]; }
        sred[16] = ts; sred[17] = tq;
    }
    __syncthreads();
    const float mean = sred[16] * (1.0f / DM);
    const float var  = sred[17] * (1.0f / DM) - mean * mean;
    const float inv  = rsqrtf(var + 1e-5f);

    float4 g = *(const float4*)&gamma[tid * 4];
    float4 bb = *(const float4*)&beta[tid * 4];
    float4 o4;
    o4.x = (v.x - mean) * inv * g.x + bb.x;
    o4.y = (v.y - mean) * inv * g.y + bb.y;
    o4.z = (v.z - mean) * inv * g.z + bb.z;
    o4.w = (v.w - mean) * inv * g.w + bb.w;
    *(float4*)&out[(size_t)blockIdx.x * DM + tid * 4] = o4;
}

// ---------------------------------------------------------------------------
extern "C" void kernel_launch(void* const* d_in, const int* in_sizes, int n_in,
                              void* d_out, int out_size)
{
    const float* q       = (const float*)d_in[0];
    const float* k       = (const float*)d_in[1];
    const float* v       = (const float*)d_in[2];
    const unsigned char* mask = (const unsigned char*)d_in[3];
    const float* w_qs    = (const float*)d_in[4];
    const float* w_ks    = (const float*)d_in[5];
    const float* w_vs    = (const float*)d_in[6];
    const float* proj_w  = (const float*)d_in[7];
    const float* proj_b  = (const float*)d_in[8];
    const float* ln_g    = (const float*)d_in[9];
    const float* ln_b    = (const float*)d_in[10];

    float* out   = (float*)d_out;
    float* attns = out + OUT_ELEMS;

    void *pqs, *pks, *pvs, *poh, *px;
    cudaGetSymbolAddress(&pqs, g_qs);
    cudaGetSymbolAddress(&pks, g_ks);
    cudaGetSymbolAddress(&pvs, g_vs);
    cudaGetSymbolAddress(&poh, g_oh);
    cudaGetSymbolAddress(&px,  g_x);
    float* gqs = (float*)pqs;
    float* gks = (float*)pks;
    float* gvs = (float*)pvs;
    float* goh = (float*)poh;
    float* gx  = (float*)px;

    dim3 gq(DM / 128, BL / 128);   // (8, 64)
    gemm_qkv<<<gq, 256>>>(q, w_qs, gqs);
    gemm_qkv<<<gq, 256>>>(k, w_ks, gks);
    gemm_qkv<<<gq, 256>>>(v, w_vs, gvs);

    scores_kernel<<<dim3(16, 16, 128), 256>>>(gqs, gks, mask, attns);
    softmax_kernel<<<128 * 1024, 256>>>(attns);
    av_kernel<<<dim3(16, 128), 256>>>(attns, gvs, goh);

    gemm_proj<<<gq, 256>>>(goh, proj_w, proj_b, q, gx);
    ln_kernel<<<BL, 256>>>(gx, ln_g, ln_b, out);
}

// round 10
// speedup vs baseline: 1.7941x; 1.7941x over previous
#include <cuda_runtime.h>
#include <cuda_bf16.h>
#include <math.h>
#include <stdint.h>

// Problem constants
#define BQ 8
#define LQ 1024
#define DM 1024
#define NH 16
#define DK 64
#define BL (BQ * LQ)          // 8192 rows
#define ATTN_ELEMS (128ull * 1024ull * 1024ull)
#define OUT_ELEMS  (8ull * 1024ull * 1024ull)

// ---------------------------------------------------------------------------
// Scratch (device globals: allocation-free rule)
// ---------------------------------------------------------------------------
__device__ __align__(256) __nv_bfloat16 g_q_h[BL * DM], g_q_l[BL * DM];
__device__ __align__(256) __nv_bfloat16 g_k_h[BL * DM], g_k_l[BL * DM];
__device__ __align__(256) __nv_bfloat16 g_v_h[BL * DM], g_v_l[BL * DM];
__device__ __align__(256) __nv_bfloat16 g_wq_h[DM * DM], g_wq_l[DM * DM];
__device__ __align__(256) __nv_bfloat16 g_wk_h[DM * DM], g_wk_l[DM * DM];
__device__ __align__(256) __nv_bfloat16 g_wv_h[DM * DM], g_wv_l[DM * DM];
__device__ __align__(256) __nv_bfloat16 g_wp_h[DM * DM], g_wp_l[DM * DM];
__device__ __align__(256) __nv_bfloat16 g_oh_h[BL * DM], g_oh_l[BL * DM];
__device__ __align__(256) float g_qs[BL * DM];
__device__ __align__(256) float g_ks[BL * DM];
__device__ __align__(256) float g_vs[BL * DM];
__device__ __align__(256) float g_x [BL * DM];

// ---------------------------------------------------------------------------
// PTX helpers (plain sm_80-era PTX; no sm_103a-only features)
// ---------------------------------------------------------------------------
__device__ __forceinline__ uint32_t smem_u32(const void* p) {
    uint32_t a;
    asm("{ .reg .u64 t; cvta.to.shared.u64 t, %1; cvt.u32.u64 %0, t; }"
        : "=r"(a) : "l"(p));
    return a;
}

static __device__ __forceinline__ void cpasync16(uint32_t saddr, const void* gptr) {
    asm volatile("cp.async.cg.shared.global [%0], [%1], 16;"
                 :: "r"(saddr), "l"(gptr) : "memory");
}
static __device__ __forceinline__ void cpasync_commit() {
    asm volatile("cp.async.commit_group;" ::: "memory");
}
static __device__ __forceinline__ void cpasync_wait0() {
    asm volatile("cp.async.wait_group 0;" ::: "memory");
}

static __device__ __forceinline__ void ldsm4(uint32_t* r, uint32_t addr) {
    asm volatile("ldmatrix.sync.aligned.m8n8.x4.shared.b16 {%0,%1,%2,%3}, [%4];"
                 : "=r"(r[0]), "=r"(r[1]), "=r"(r[2]), "=r"(r[3]) : "r"(addr));
}

static __device__ __forceinline__ void mma16816(float* d, const uint32_t* a,
                                                uint32_t b0, uint32_t b1) {
    asm volatile("mma.sync.aligned.m16n8k16.row.col.f32.bf16.bf16.f32 "
                 "{%0,%1,%2,%3}, {%4,%5,%6,%7}, {%8,%9}, {%0,%1,%2,%3};"
                 : "+f"(d[0]), "+f"(d[1]), "+f"(d[2]), "+f"(d[3])
                 : "r"(a[0]), "r"(a[1]), "r"(a[2]), "r"(a[3]), "r"(b0), "r"(b1));
}

// ---------------------------------------------------------------------------
// fp32 -> (bf16 hi, bf16 lo) split: elementwise
// ---------------------------------------------------------------------------
__global__ __launch_bounds__(256) void split_fp32(const float* __restrict__ in,
                                                  __nv_bfloat16* __restrict__ hi,
                                                  __nv_bfloat16* __restrict__ lo,
                                                  int n4)
{
    int i = blockIdx.x * 256 + threadIdx.x;
    if (i >= n4) return;
    float4 v = *(const float4*)(in + (size_t)i * 4);
    float h0 = __bfloat162float(__float2bfloat16_rn(v.x));
    float h1 = __bfloat162float(__float2bfloat16_rn(v.y));
    float h2 = __bfloat162float(__float2bfloat16_rn(v.z));
    float h3 = __bfloat162float(__float2bfloat16_rn(v.w));
    __nv_bfloat162* hp = (__nv_bfloat162*)(hi + (size_t)i * 4);
    __nv_bfloat162* lp = (__nv_bfloat162*)(lo + (size_t)i * 4);
    hp[0] = __floats2bfloat162_rn(h0, h1);
    hp[1] = __floats2bfloat162_rn(h2, h3);
    lp[0] = __floats2bfloat162_rn(v.x - h0, v.y - h1);
    lp[1] = __floats2bfloat162_rn(v.z - h2, v.w - h3);
}

// ---------------------------------------------------------------------------
// Head-weight convert+transpose: B[n][d] = W[h=n>>6][d][kk=n&63], split bf16
// ---------------------------------------------------------------------------
__global__ __launch_bounds__(256) void wqkv_split(const float* __restrict__ W,
                                                  __nv_bfloat16* __restrict__ hi,
                                                  __nv_bfloat16* __restrict__ lo)
{
    int idx = blockIdx.x * 256 + threadIdx.x;     // = n*1024 + d, d fastest
    int d = idx & 1023;
    int n = idx >> 10;
    float x = W[(size_t)(((n >> 6) << 10) + d) * 64 + (n & 63)];
    float h = __bfloat162float(__float2bfloat16_rn(x));
    hi[idx] = __float2bfloat16_rn(x);
    lo[idx] = __float2bfloat16_rn(x - h);
}

// ---------------------------------------------------------------------------
// bf16-split HMMA GEMM: C[m,n] = sum_k A[m,k]*B[n,k] (+bias[n]+resid[m,n])
// A pair [8192x1024], B pair [1024x1024] K-major rows.
// CTA tile 128(M) x 64(N), 8 warps in 4x2 grid, warp tile 32x32.
// BK=32, cp.async double-buffered, 80B-padded smem rows (conflict-free LDSM).
// 3 MMAs (hh, hl, lh) per m16n8k16 step.
// ---------------------------------------------------------------------------
#define ROWB 80                       // bytes per smem row (32 bf16 + pad)
#define A_HI 0
#define A_LO (128 * ROWB)             // 10240
#define B_HI (2 * 128 * ROWB)         // 20480
#define B_LO (2 * 128 * ROWB + 64 * ROWB)  // 25600
#define BUFB (2 * 128 * ROWB + 2 * 64 * ROWB) // 30720
#define GEMM_SMEM (2 * BUFB)          // 61440

__global__ __launch_bounds__(256) void gemm_bf16x2(
    const __nv_bfloat16* __restrict__ Ah, const __nv_bfloat16* __restrict__ Al,
    const __nv_bfloat16* __restrict__ Bh, const __nv_bfloat16* __restrict__ Bl,
    float* __restrict__ C, const float* __restrict__ bias,
    const float* __restrict__ resid)
{
    extern __shared__ __align__(128) char smem[];
    const uint32_t sb = smem_u32(smem);
    const int tid = threadIdx.x;
    const int wid = tid >> 5;
    const int lane = tid & 31;
    const int n0 = blockIdx.x * 64;
    const int m0 = blockIdx.y * 128;
    const int warp_m = wid >> 1;          // 0..3
    const int warp_n = wid & 1;           // 0..1

    // cp.async task coords
    const int ar0 = tid >> 2;             // A rows handled: ar0, ar0+64
    const int ac  = (tid & 3);            // 16B unit
    const int br  = tid >> 2;             // B row 0..63
    // ldmatrix lane offsets (byte units within a tile)
    const int lr = lane & 15;
    const int lc = (lane >> 4) & 1;
    const uint32_t a_l_off = (uint32_t)((warp_m * 32 + lr) * ROWB + lc * 16);
    const uint32_t b_l_off = (uint32_t)((warp_n * 32 + lr) * ROWB + lc * 16);

    float acc[2][4][4];
    #pragma unroll
    for (int mt = 0; mt < 2; mt++)
        #pragma unroll
        for (int nt = 0; nt < 4; nt++)
            #pragma unroll
            for (int e = 0; e < 4; e++) acc[mt][nt][e] = 0.f;

    auto load_chunk = [&](int kc, uint32_t bb) {
        const int kk = kc * 32 + ac * 8;
        #pragma unroll
        for (int t = 0; t < 2; t++) {
            int r = ar0 + t * 64;
            uint32_t s = bb + (uint32_t)(r * ROWB + ac * 16);
            const __nv_bfloat16* gh = Ah + (size_t)(m0 + r) * DM + kk;
            const __nv_bfloat16* gl = Al + (size_t)(m0 + r) * DM + kk;
            cpasync16(s + A_HI, gh);
            cpasync16(s + A_LO, gl);
        }
        {
            uint32_t s = bb + (uint32_t)(br * ROWB + ac * 16);
            cpasync16(s + B_HI, Bh + (size_t)(n0 + br) * DM + kk);
            cpasync16(s + B_LO, Bl + (size_t)(n0 + br) * DM + kk);
        }
    };

    load_chunk(0, sb);
    cpasync_commit();

    const int NC = DM / 32;               // 32
    for (int kc = 0; kc < NC; kc++) {
        cpasync_wait0();
        __syncthreads();
        const uint32_t bb = sb + (uint32_t)((kc & 1) * BUFB);
        if (kc + 1 < NC) {
            load_chunk(kc + 1, sb + (uint32_t)(((kc + 1) & 1) * BUFB));
            cpasync_commit();
        } else {
            cpasync_commit();             // keep wait_group balanced
        }

        #pragma unroll
        for (int ks = 0; ks < 2; ks++) {
            uint32_t ah[2][4], al[2][4], bh[2][4], bl[2][4];
            #pragma unroll
            for (int mt = 0; mt < 2; mt++) {
                uint32_t ao = bb + a_l_off + (uint32_t)(mt * 16 * ROWB + ks * 32);
                ldsm4(ah[mt], ao + A_HI);
                ldsm4(al[mt], ao + A_LO);
            }
            #pragma unroll
            for (int nt2 = 0; nt2 < 2; nt2++) {
                uint32_t bo = bb + b_l_off + (uint32_t)(nt2 * 16 * ROWB + ks * 32);
                ldsm4(bh[nt2], bo + B_HI);
                ldsm4(bl[nt2], bo + B_LO);
            }
            #pragma unroll
            for (int mt = 0; mt < 2; mt++) {
                #pragma unroll
                for (int nt = 0; nt < 4; nt++) {
                    const int g = nt >> 1, s = nt & 1;
                    mma16816(acc[mt][nt], ah[mt], bh[g][s], bh[g][2 + s]);
                    mma16816(acc[mt][nt], ah[mt], bl[g][s], bl[g][2 + s]);
                    mma16816(acc[mt][nt], al[mt], bh[g][s], bh[g][2 + s]);
                }
            }
        }
        __syncthreads();
    }

    // Epilogue: thread (lane) holds rows lane>>2 (+8), cols (lane&3)*2 (+1)
    const int erow = m0 + warp_m * 32 + (lane >> 2);
    const int ecol = n0 + warp_n * 32 + (lane & 3) * 2;
    #pragma unroll
    for (int mt = 0; mt < 2; mt++) {
        #pragma unroll
        for (int nt = 0; nt < 4; nt++) {
            int m = erow + mt * 16;
            int n = ecol + nt * 8;
            float2 v0 = make_float2(acc[mt][nt][0], acc[mt][nt][1]);
            float2 v1 = make_float2(acc[mt][nt][2], acc[mt][nt][3]);
            if (bias != nullptr) {
                v0.x += bias[n]     + resid[(size_t)m * DM + n];
                v0.y += bias[n + 1] + resid[(size_t)m * DM + n + 1];
                v1.x += bias[n]     + resid[(size_t)(m + 8) * DM + n];
                v1.y += bias[n + 1] + resid[(size_t)(m + 8) * DM + n + 1];
            }
            *(float2*)&C[(size_t)m * DM + n]       = v0;
            *(float2*)&C[(size_t)(m + 8) * DM + n] = v1;
        }
    }
}

// ---------------------------------------------------------------------------
// Scores: S[hb,i,j] = (Qs[b,i,h*64+:] . Ks[b,j,h*64+:]) / 32, mask -> -inf
// 128x128 tile, BK=16, 8x8 micro.
// ---------------------------------------------------------------------------
__global__ __launch_bounds__(256) void scores_kernel(const float* __restrict__ Qs,
                                                     const float* __restrict__ Ks,
                                                     const unsigned char* __restrict__ mask,
                                                     float* __restrict__ attns)
{
    __shared__ float Qt[16][132];
    __shared__ float Kt[16][132];
    const int j0 = blockIdx.x * 128;
    const int i0 = blockIdx.y * 128;
    const int hb = blockIdx.z;
    const int h = hb >> 3;
    const int b = hb & 7;
    const int tid = threadIdx.x;
    const int base = b * LQ;
    const int hc = h * DK;
    const int r0 = (tid >> 4) * 8;
    const int c0 = (tid & 15) * 8;
    const int lr = tid >> 1;
    const int dg = (tid & 1) * 8;

    float acc[8][8];
    #pragma unroll
    for (int i = 0; i < 8; i++)
        #pragma unroll
        for (int j = 0; j < 8; j++) acc[i][j] = 0.f;

    for (int k0 = 0; k0 < DK; k0 += 16) {
        float4 q1 = *(const float4*)&Qs[(size_t)(base + i0 + lr) * DM + hc + k0 + dg];
        float4 q2 = *(const float4*)&Qs[(size_t)(base + i0 + lr) * DM + hc + k0 + dg + 4];
        float4 k1 = *(const float4*)&Ks[(size_t)(base + j0 + lr) * DM + hc + k0 + dg];
        float4 k2 = *(const float4*)&Ks[(size_t)(base + j0 + lr) * DM + hc + k0 + dg + 4];
        Qt[dg + 0][lr] = q1.x; Qt[dg + 1][lr] = q1.y; Qt[dg + 2][lr] = q1.z; Qt[dg + 3][lr] = q1.w;
        Qt[dg + 4][lr] = q2.x; Qt[dg + 5][lr] = q2.y; Qt[dg + 6][lr] = q2.z; Qt[dg + 7][lr] = q2.w;
        Kt[dg + 0][lr] = k1.x; Kt[dg + 1][lr] = k1.y; Kt[dg + 2][lr] = k1.z; Kt[dg + 3][lr] = k1.w;
        Kt[dg + 4][lr] = k2.x; Kt[dg + 5][lr] = k2.y; Kt[dg + 6][lr] = k2.z; Kt[dg + 7][lr] = k2.w;
        __syncthreads();
        #pragma unroll
        for (int d = 0; d < 16; d++) {
            float a[8], bv[8];
            *(float4*)(a)      = *(const float4*)&Qt[d][r0];
            *(float4*)(a + 4)  = *(const float4*)&Qt[d][r0 + 4];
            *(float4*)(bv)     = *(const float4*)&Kt[d][c0];
            *(float4*)(bv + 4) = *(const float4*)&Kt[d][c0 + 4];
            #pragma unroll
            for (int i = 0; i < 8; i++)
                #pragma unroll
                for (int j = 0; j < 8; j++)
                    acc[i][j] += a[i] * bv[j];
        }
        __syncthreads();
    }

    const float scale = 0.03125f;   // 1/sqrt(1024)
    #pragma unroll
    for (int i = 0; i < 8; i++) {
        int gi = i0 + r0 + i;
        const unsigned char* mrow = &mask[((size_t)b * LQ + gi) * LQ + j0 + c0];
        float* orow = &attns[((size_t)hb * LQ + gi) * LQ + j0 + c0];
        float o[8];
        #pragma unroll
        for (int j = 0; j < 8; j++) {
            float s = acc[i][j] * scale;
            if (mrow[j]) s = -INFINITY;
            o[j] = s;
        }
        *(float4*)&orow[0] = *(float4*)&o[0];
        *(float4*)&orow[4] = *(float4*)&o[4];
    }
}

// ---------------------------------------------------------------------------
// FMA-only exp (no MUFU): exp(x) = 2^(x*log2e), poly on [-0.5, 0.5]
// ---------------------------------------------------------------------------
static __device__ __forceinline__ float fexp(float x)
{
    x = fmaxf(x, -80.0f);
    float y = x * 1.4426950408889634f;
    float n = rintf(y);
    float f = y - n;
    float p = 1.3371541e-4f;
    p = fmaf(p, f, 1.3333558e-3f);
    p = fmaf(p, f, 9.6181291e-3f);
    p = fmaf(p, f, 5.5504109e-2f);
    p = fmaf(p, f, 2.4022651e-1f);
    p = fmaf(p, f, 6.9314718e-1f);
    p = fmaf(p, f, 1.0f);
    float s = __int_as_float(((int)n + 127) << 23);
    return p * s;
}

// ---------------------------------------------------------------------------
// Softmax: one warp per row of 1024, values held in registers.
// ---------------------------------------------------------------------------
__global__ __launch_bounds__(256) void softmax_kernel(float* __restrict__ attns)
{
    const int row = blockIdx.x * 8 + (threadIdx.x >> 5);
    const int lid = threadIdx.x & 31;
    float* p = attns + (size_t)row * 1024 + lid * 4;

    float4 v[8];
    #pragma unroll
    for (int t = 0; t < 8; t++) v[t] = *(const float4*)(p + t * 128);

    float m = -INFINITY;
    #pragma unroll
    for (int t = 0; t < 8; t++)
        m = fmaxf(m, fmaxf(fmaxf(v[t].x, v[t].y), fmaxf(v[t].z, v[t].w)));
    #pragma unroll
    for (int o = 16; o; o >>= 1) m = fmaxf(m, __shfl_xor_sync(0xffffffffu, m, o));

    float s = 0.f;
    #pragma unroll
    for (int t = 0; t < 8; t++) {
        v[t].x = fexp(v[t].x - m); v[t].y = fexp(v[t].y - m);
        v[t].z = fexp(v[t].z - m); v[t].w = fexp(v[t].w - m);
        s += v[t].x + v[t].y + v[t].z + v[t].w;
    }
    #pragma unroll
    for (int o = 16; o; o >>= 1) s += __shfl_xor_sync(0xffffffffu, s, o);
    const float inv = 1.0f / s;

    #pragma unroll
    for (int t = 0; t < 8; t++) {
        float4 o4 = make_float4(v[t].x * inv, v[t].y * inv, v[t].z * inv, v[t].w * inv);
        *(float4*)(p + t * 128) = o4;
    }
}

// ---------------------------------------------------------------------------
// AV: Oh[b,i,h*64+v] = sum_j attn[hb,i,j] * Vs[b,j,h*64+v]
// 128(i) x 64(v) tile, K chunk 32, 8x4 micro. Emits bf16 hi/lo pair directly.
// ---------------------------------------------------------------------------
__global__ __launch_bounds__(256) void av_kernel(const float* __restrict__ attns,
                                                 const float* __restrict__ Vs,
                                                 __nv_bfloat16* __restrict__ Oh,
                                                 __nv_bfloat16* __restrict__ Ol)
{
    __shared__ float At[32][132];
    __shared__ float Vt[32][68];
    const int i0 = blockIdx.x * 128;
    const int hb = blockIdx.y;
    const int h = hb >> 3;
    const int b = hb & 7;
    const int tid = threadIdx.x;
    const float* arow = attns + (size_t)hb * LQ * LQ;
    const int hc = h * DK;

    const int ti = (tid >> 4) * 8;
    const int tv = (tid & 15) * 4;
    const int lr = tid >> 1;             // 0..127 (i row for At loads)
    const int jg = (tid & 1) * 16;       // j group
    const int r2 = tid >> 3;             // 0..31 (j row for Vt loads)
    const int c2 = (tid & 7) * 8;        // v col group

    float acc[8][4];
    #pragma unroll
    for (int i = 0; i < 8; i++)
        #pragma unroll
        for (int j = 0; j < 4; j++) acc[i][j] = 0.f;

    for (int j0 = 0; j0 < LQ; j0 += 32) {
        #pragma unroll
        for (int s = 0; s < 4; s++) {
            float4 x = *(const float4*)&arow[(size_t)(i0 + lr) * LQ + j0 + jg + s * 4];
            At[jg + s * 4 + 0][lr] = x.x;
            At[jg + s * 4 + 1][lr] = x.y;
            At[jg + s * 4 + 2][lr] = x.z;
            At[jg + s * 4 + 3][lr] = x.w;
        }
        {
            const float* vp = &Vs[((size_t)b * LQ + j0 + r2) * DM + hc + c2];
            *(float4*)&Vt[r2][c2]     = *(const float4*)vp;
            *(float4*)&Vt[r2][c2 + 4] = *(const float4*)(vp + 4);
        }
        __syncthreads();
        #pragma unroll
        for (int d = 0; d < 32; d++) {
            float a[8], bv[4];
            *(float4*)(a)     = *(const float4*)&At[d][ti];
            *(float4*)(a + 4) = *(const float4*)&At[d][ti + 4];
            *(float4*)(bv)    = *(const float4*)&Vt[d][tv];
            #pragma unroll
            for (int i = 0; i < 8; i++)
                #pragma unroll
                for (int j = 0; j < 4; j++)
                    acc[i][j] += a[i] * bv[j];
        }
        __syncthreads();
    }

    #pragma unroll
    for (int i = 0; i < 8; i++) {
        size_t off = ((size_t)b * LQ + i0 + ti + i) * DM + hc + tv;
        float h0 = __bfloat162float(__float2bfloat16_rn(acc[i][0]));
        float h1 = __bfloat162float(__float2bfloat16_rn(acc[i][1]));
        float h2 = __bfloat162float(__float2bfloat16_rn(acc[i][2]));
        float h3 = __bfloat162float(__float2bfloat16_rn(acc[i][3]));
        *(__nv_bfloat162*)&Oh[off]     = __floats2bfloat162_rn(h0, h1);
        *(__nv_bfloat162*)&Oh[off + 2] = __floats2bfloat162_rn(h2, h3);
        *(__nv_bfloat162*)&Ol[off]     = __floats2bfloat162_rn(acc[i][0] - h0, acc[i][1] - h1);
        *(__nv_bfloat162*)&Ol[off + 2] = __floats2bfloat162_rn(acc[i][2] - h2, acc[i][3] - h3);
    }
}

// ---------------------------------------------------------------------------
// LayerNorm: one block per row of 1024.
// ---------------------------------------------------------------------------
__global__ __launch_bounds__(256) void ln_kernel(const float* __restrict__ X,
                                                 const float* __restrict__ gamma,
                                                 const float* __restrict__ beta,
                                                 float* __restrict__ out)
{
    __shared__ float sred[32];
    const float* p = X + (size_t)blockIdx.x * DM;
    const int tid = threadIdx.x;

    float4 v = *(const float4*)&p[tid * 4];
    float s  = v.x + v.y + v.z + v.w;
    float sq = v.x * v.x + v.y * v.y + v.z * v.z + v.w * v.w;
    #pragma unroll
    for (int o = 16; o; o >>= 1) {
        s  += __shfl_xor_sync(0xffffffffu, s,  o);
        sq += __shfl_xor_sync(0xffffffffu, sq, o);
    }
    if ((tid & 31) == 0) { sred[tid >> 5] = s; sred[8 + (tid >> 5)] = sq; }
    __syncthreads();
    if (tid == 0) {
        float ts = 0.f, tq = 0.f;
        #pragma unroll
        for (int i = 0; i < 8; i++) { ts += sred[i]; tq += sred[8 + i]; }
        sred[16] = ts; sred[17] = tq;
    }
    __syncthreads();
    const float mean = sred[16] * (1.0f / DM);
    const float var  = sred[17] * (1.0f / DM) - mean * mean;
    const float inv  = rsqrtf(var + 1e-5f);

    float4 g  = *(const float4*)&gamma[tid * 4];
    float4 bb = *(const float4*)&beta[tid * 4];
    float4 o4;
    o4.x = (v.x - mean) * inv * g.x + bb.x;
    o4.y = (v.y - mean) * inv * g.y + bb.y;
    o4.z = (v.z - mean) * inv * g.z + bb.z;
    o4.w = (v.w - mean) * inv * g.w + bb.w;
    *(float4*)&out[(size_t)blockIdx.x * DM + tid * 4] = o4;
}

// ---------------------------------------------------------------------------
extern "C" void kernel_launch(void* const* d_in, const int* in_sizes, int n_in,
                              void* d_out, int out_size)
{
    const float* q       = (const float*)d_in[0];
    const float* k       = (const float*)d_in[1];
    const float* v       = (const float*)d_in[2];
    const unsigned char* mask = (const unsigned char*)d_in[3];
    const float* w_qs    = (const float*)d_in[4];
    const float* w_ks    = (const float*)d_in[5];
    const float* w_vs    = (const float*)d_in[6];
    const float* proj_w  = (const float*)d_in[7];
    const float* proj_b  = (const float*)d_in[8];
    const float* ln_g    = (const float*)d_in[9];
    const float* ln_b    = (const float*)d_in[10];

    float* out   = (float*)d_out;
    float* attns = out + OUT_ELEMS;

    #define SYM(T, name) T* name; { void* p_; cudaGetSymbolAddress(&p_, g_##name); name = (T*)p_; }
    SYM(__nv_bfloat16, q_h)  SYM(__nv_bfloat16, q_l)
    SYM(__nv_bfloat16, k_h)  SYM(__nv_bfloat16, k_l)
    SYM(__nv_bfloat16, v_h)  SYM(__nv_bfloat16, v_l)
    SYM(__nv_bfloat16, wq_h) SYM(__nv_bfloat16, wq_l)
    SYM(__nv_bfloat16, wk_h) SYM(__nv_bfloat16, wk_l)
    SYM(__nv_bfloat16, wv_h) SYM(__nv_bfloat16, wv_l)
    SYM(__nv_bfloat16, wp_h) SYM(__nv_bfloat16, wp_l)
    SYM(__nv_bfloat16, oh_h) SYM(__nv_bfloat16, oh_l)
    SYM(float, qs) SYM(float, ks) SYM(float, vs) SYM(float, x)
    #undef SYM

    cudaFuncSetAttribute(gemm_bf16x2, cudaFuncAttributeMaxDynamicSharedMemorySize, GEMM_SMEM);

    // 1. split inputs and weights to bf16 hi/lo
    const int n4_in = BL * DM / 4;       // 2097152
    split_fp32<<<n4_in / 256, 256>>>(q, q_h, q_l, n4_in);
    split_fp32<<<n4_in / 256, 256>>>(k, k_h, k_l, n4_in);
    split_fp32<<<n4_in / 256, 256>>>(v, v_h, v_l, n4_in);
    const int n4_w = DM * DM / 4;        // 262144
    split_fp32<<<n4_w / 256, 256>>>(proj_w, wp_h, wp_l, n4_w);
    wqkv_split<<<DM * DM / 256, 256>>>(w_qs, wq_h, wq_l);
    wqkv_split<<<DM * DM / 256, 256>>>(w_ks, wk_h, wk_l);
    wqkv_split<<<DM * DM / 256, 256>>>(w_vs, wv_h, wv_l);

    // 2. QKV projections (HMMA bf16-split)
    dim3 gg(DM / 64, BL / 128);          // (16, 64)
    gemm_bf16x2<<<gg, 256, GEMM_SMEM>>>(q_h, q_l, wq_h, wq_l, qs, nullptr, nullptr);
    gemm_bf16x2<<<gg, 256, GEMM_SMEM>>>(k_h, k_l, wk_h, wk_l, ks, nullptr, nullptr);
    gemm_bf16x2<<<gg, 256, GEMM_SMEM>>>(v_h, v_l, wv_h, wv_l, vs, nullptr, nullptr);

    // 3. attention
    scores_kernel<<<dim3(8, 8, 128), 256>>>(qs, ks, mask, attns);
    softmax_kernel<<<128 * 1024 / 8, 256>>>(attns);
    av_kernel<<<dim3(8, 128), 256>>>(attns, vs, oh_h, oh_l);

    // 4. output projection (HMMA, fused bias + residual) and LN
    gemm_bf16x2<<<gg, 256, GEMM_SMEM>>>(oh_h, oh_l, wp_h, wp_l, x, proj_b, q);
    ln_kernel<<<BL, 256>>>(x, ln_g, ln_b, out);
}

// round 17
// speedup vs baseline: 2.1036x; 1.1725x over previous
#include <cuda_runtime.h>
#include <cuda_bf16.h>
#include <math.h>
#include <stdint.h>
#include <string.h>

// Problem constants
#define BQ 8
#define LQ 1024
#define DM 1024
#define NH 16
#define DK 64
#define BL (BQ * LQ)          // 8192 rows
#define ATTN_ELEMS (128ull * 1024ull * 1024ull)
#define OUT_ELEMS  (8ull * 1024ull * 1024ull)

typedef __nv_bfloat16 bf16;

// ---------------------------------------------------------------------------
// Scratch (device globals: allocation-free rule)
// ---------------------------------------------------------------------------
__device__ __align__(256) bf16 g_q_h[BL * DM], g_q_l[BL * DM];
__device__ __align__(256) bf16 g_k_h[BL * DM], g_k_l[BL * DM];
__device__ __align__(256) bf16 g_v_h[BL * DM], g_v_l[BL * DM];
__device__ __align__(256) bf16 g_wq_h[DM * DM], g_wq_l[DM * DM];
__device__ __align__(256) bf16 g_wk_h[DM * DM], g_wk_l[DM * DM];
__device__ __align__(256) bf16 g_wv_h[DM * DM], g_wv_l[DM * DM];
__device__ __align__(256) bf16 g_wp_h[DM * DM], g_wp_l[DM * DM];
__device__ __align__(256) bf16 g_pq_h[BL * DM], g_pq_l[BL * DM];   // projected Q hi/lo
__device__ __align__(256) bf16 g_pk_h[BL * DM], g_pk_l[BL * DM];   // projected K hi/lo
__device__ __align__(256) bf16 g_pv_h[BL * DM], g_pv_l[BL * DM];   // projected V hi/lo
__device__ __align__(256) bf16 g_oh_h[BL * DM], g_oh_l[BL * DM];
__device__ __align__(256) float g_x[BL * DM];

// ---------------------------------------------------------------------------
// PTX helpers (plain sm_80-era PTX; no sm_103a-only features)
// ---------------------------------------------------------------------------
__device__ __forceinline__ uint32_t smem_u32(const void* p) {
    uint32_t a;
    asm("{ .reg .u64 t; cvta.to.shared.u64 t, %1; cvt.u32.u64 %0, t; }"
        : "=r"(a) : "l"(p));
    return a;
}
static __device__ __forceinline__ void cpasync16(uint32_t saddr, const void* gptr) {
    asm volatile("cp.async.cg.shared.global [%0], [%1], 16;"
                 :: "r"(saddr), "l"(gptr) : "memory");
}
static __device__ __forceinline__ void cpasync_commit() {
    asm volatile("cp.async.commit_group;" ::: "memory");
}
static __device__ __forceinline__ void cpasync_wait0() {
    asm volatile("cp.async.wait_group 0;" ::: "memory");
}
static __device__ __forceinline__ void ldsm4(uint32_t* r, uint32_t addr) {
    asm volatile("ldmatrix.sync.aligned.m8n8.x4.shared.b16 {%0,%1,%2,%3}, [%4];"
                 : "=r"(r[0]), "=r"(r[1]), "=r"(r[2]), "=r"(r[3]) : "r"(addr));
}
static __device__ __forceinline__ void ldsm4t(uint32_t* r, uint32_t addr) {
    asm volatile("ldmatrix.sync.aligned.m8n8.x4.trans.shared.b16 {%0,%1,%2,%3}, [%4];"
                 : "=r"(r[0]), "=r"(r[1]), "=r"(r[2]), "=r"(r[3]) : "r"(addr));
}
static __device__ __forceinline__ void mma16816(float* d, const uint32_t* a,
                                                uint32_t b0, uint32_t b1) {
    asm volatile("mma.sync.aligned.m16n8k16.row.col.f32.bf16.bf16.f32 "
                 "{%0,%1,%2,%3}, {%4,%5,%6,%7}, {%8,%9}, {%0,%1,%2,%3};"
                 : "+f"(d[0]), "+f"(d[1]), "+f"(d[2]), "+f"(d[3])
                 : "r"(a[0]), "r"(a[1]), "r"(a[2]), "r"(a[3]), "r"(b0), "r"(b1));
}
static __device__ __forceinline__ uint32_t bf2_as_u32(__nv_bfloat162 v) {
    uint32_t u;
    memcpy(&u, &v, 4);
    return u;
}

// ---------------------------------------------------------------------------
// FMA-only exp (no MUFU): exp(x) = 2^(x*log2e), poly on [-0.5, 0.5]
// ---------------------------------------------------------------------------
static __device__ __forceinline__ float fexp(float x)
{
    x = fmaxf(x, -80.0f);
    float y = x * 1.4426950408889634f;
    float n = rintf(y);
    float f = y - n;
    float p = 1.3371541e-4f;
    p = fmaf(p, f, 1.3333558e-3f);
    p = fmaf(p, f, 9.6181291e-3f);
    p = fmaf(p, f, 5.5504109e-2f);
    p = fmaf(p, f, 2.4022651e-1f);
    p = fmaf(p, f, 6.9314718e-1f);
    p = fmaf(p, f, 1.0f);
    float s = __int_as_float(((int)n + 127) << 23);
    return p * s;
}

// ---------------------------------------------------------------------------
// fp32 -> (bf16 hi, bf16 lo) split: elementwise
// ---------------------------------------------------------------------------
__global__ __launch_bounds__(256) void split_fp32(const float* __restrict__ in,
                                                  bf16* __restrict__ hi,
                                                  bf16* __restrict__ lo,
                                                  int n4)
{
    int i = blockIdx.x * 256 + threadIdx.x;
    if (i >= n4) return;
    float4 v = *(const float4*)(in + (size_t)i * 4);
    float h0 = __bfloat162float(__float2bfloat16_rn(v.x));
    float h1 = __bfloat162float(__float2bfloat16_rn(v.y));
    float h2 = __bfloat162float(__float2bfloat16_rn(v.z));
    float h3 = __bfloat162float(__float2bfloat16_rn(v.w));
    __nv_bfloat162* hp = (__nv_bfloat162*)(hi + (size_t)i * 4);
    __nv_bfloat162* lp = (__nv_bfloat162*)(lo + (size_t)i * 4);
    hp[0] = __floats2bfloat162_rn(h0, h1);
    hp[1] = __floats2bfloat162_rn(h2, h3);
    lp[0] = __floats2bfloat162_rn(v.x - h0, v.y - h1);
    lp[1] = __floats2bfloat162_rn(v.z - h2, v.w - h3);
}

// ---------------------------------------------------------------------------
// Head-weight convert+transpose: B[n][d] = W[h=n>>6][d][kk=n&63], split bf16
// ---------------------------------------------------------------------------
__global__ __launch_bounds__(256) void wqkv_split(const float* __restrict__ W,
                                                  bf16* __restrict__ hi,
                                                  bf16* __restrict__ lo)
{
    int idx = blockIdx.x * 256 + threadIdx.x;
    int d = idx & 1023;
    int n = idx >> 10;
    float x = W[(size_t)(((n >> 6) << 10) + d) * 64 + (n & 63)];
    float h = __bfloat162float(__float2bfloat16_rn(x));
    hi[idx] = __float2bfloat16_rn(x);
    lo[idx] = __float2bfloat16_rn(x - h);
}

// ---------------------------------------------------------------------------
// bf16-split HMMA GEMM: acc[m,n] = sum_k A[m,k]*B[n,k]
// Template OUT: 0 = fp32 C with bias+resid (proj); 1 = bf16 hi/lo outputs.
// CTA 128(M)x64(N), 8 warps 4x2, warp tile 32x32, BK=32, double-buffered.
// ---------------------------------------------------------------------------
#define ROWB 80
#define A_HI 0
#define A_LO (128 * ROWB)
#define B_HI (2 * 128 * ROWB)
#define B_LO (2 * 128 * ROWB + 64 * ROWB)
#define BUFB (2 * 128 * ROWB + 2 * 64 * ROWB)
#define GEMM_SMEM (2 * BUFB)          // 61440

template <int OUTBF16>
__global__ __launch_bounds__(256) void gemm_bf16x2(
    const bf16* __restrict__ Ah, const bf16* __restrict__ Al,
    const bf16* __restrict__ Bh, const bf16* __restrict__ Bl,
    float* __restrict__ C, bf16* __restrict__ Ch, bf16* __restrict__ Cl,
    const float* __restrict__ bias, const float* __restrict__ resid)
{
    extern __shared__ __align__(128) char smem[];
    const uint32_t sb = smem_u32(smem);
    const int tid = threadIdx.x;
    const int wid = tid >> 5;
    const int lane = tid & 31;
    const int n0 = blockIdx.x * 64;
    const int m0 = blockIdx.y * 128;
    const int warp_m = wid >> 1;
    const int warp_n = wid & 1;

    const int ar0 = tid >> 2;
    const int ac  = (tid & 3);
    const int br  = tid >> 2;
    const int lr = lane & 15;
    const int lc = (lane >> 4) & 1;
    const uint32_t a_l_off = (uint32_t)((warp_m * 32 + lr) * ROWB + lc * 16);
    const uint32_t b_l_off = (uint32_t)((warp_n * 32 + lr) * ROWB + lc * 16);

    float acc[2][4][4];
    #pragma unroll
    for (int mt = 0; mt < 2; mt++)
        #pragma unroll
        for (int nt = 0; nt < 4; nt++)
            #pragma unroll
            for (int e = 0; e < 4; e++) acc[mt][nt][e] = 0.f;

    auto load_chunk = [&](int kc, uint32_t bb) {
        const int kk = kc * 32 + ac * 8;
        #pragma unroll
        for (int t = 0; t < 2; t++) {
            int r = ar0 + t * 64;
            uint32_t s = bb + (uint32_t)(r * ROWB + ac * 16);
            cpasync16(s + A_HI, Ah + (size_t)(m0 + r) * DM + kk);
            cpasync16(s + A_LO, Al + (size_t)(m0 + r) * DM + kk);
        }
        {
            uint32_t s = bb + (uint32_t)(br * ROWB + ac * 16);
            cpasync16(s + B_HI, Bh + (size_t)(n0 + br) * DM + kk);
            cpasync16(s + B_LO, Bl + (size_t)(n0 + br) * DM + kk);
        }
    };

    load_chunk(0, sb);
    cpasync_commit();

    const int NC = DM / 32;
    for (int kc = 0; kc < NC; kc++) {
        cpasync_wait0();
        __syncthreads();
        const uint32_t bb = sb + (uint32_t)((kc & 1) * BUFB);
        if (kc + 1 < NC) {
            load_chunk(kc + 1, sb + (uint32_t)(((kc + 1) & 1) * BUFB));
            cpasync_commit();
        } else {
            cpasync_commit();
        }

        #pragma unroll
        for (int ks = 0; ks < 2; ks++) {
            uint32_t ah[2][4], al[2][4], bh[2][4], bl[2][4];
            #pragma unroll
            for (int mt = 0; mt < 2; mt++) {
                uint32_t ao = bb + a_l_off + (uint32_t)(mt * 16 * ROWB + ks * 32);
                ldsm4(ah[mt], ao + A_HI);
                ldsm4(al[mt], ao + A_LO);
            }
            #pragma unroll
            for (int nt2 = 0; nt2 < 2; nt2++) {
                uint32_t bo = bb + b_l_off + (uint32_t)(nt2 * 16 * ROWB + ks * 32);
                ldsm4(bh[nt2], bo + B_HI);
                ldsm4(bl[nt2], bo + B_LO);
            }
            #pragma unroll
            for (int mt = 0; mt < 2; mt++) {
                #pragma unroll
                for (int nt = 0; nt < 4; nt++) {
                    const int g = nt >> 1, s = nt & 1;
                    mma16816(acc[mt][nt], ah[mt], bh[g][s], bh[g][2 + s]);
                    mma16816(acc[mt][nt], ah[mt], bl[g][s], bl[g][2 + s]);
                    mma16816(acc[mt][nt], al[mt], bh[g][s], bh[g][2 + s]);
                }
            }
        }
        __syncthreads();
    }

    const int erow = m0 + warp_m * 32 + (lane >> 2);
    const int ecol = n0 + warp_n * 32 + (lane & 3) * 2;
    #pragma unroll
    for (int mt = 0; mt < 2; mt++) {
        #pragma unroll
        for (int nt = 0; nt < 4; nt++) {
            int m = erow + mt * 16;
            int n = ecol + nt * 8;
            if (OUTBF16) {
                #pragma unroll
                for (int half = 0; half < 2; half++) {
                    int mm = m + half * 8;
                    float a0 = acc[mt][nt][half * 2 + 0];
                    float a1 = acc[mt][nt][half * 2 + 1];
                    float h0 = __bfloat162float(__float2bfloat16_rn(a0));
                    float h1 = __bfloat162float(__float2bfloat16_rn(a1));
                    *(__nv_bfloat162*)&Ch[(size_t)mm * DM + n] = __floats2bfloat162_rn(h0, h1);
                    *(__nv_bfloat162*)&Cl[(size_t)mm * DM + n] = __floats2bfloat162_rn(a0 - h0, a1 - h1);
                }
            } else {
                float2 v0 = make_float2(acc[mt][nt][0], acc[mt][nt][1]);
                float2 v1 = make_float2(acc[mt][nt][2], acc[mt][nt][3]);
                v0.x += bias[n]     + resid[(size_t)m * DM + n];
                v0.y += bias[n + 1] + resid[(size_t)m * DM + n + 1];
                v1.x += bias[n]     + resid[(size_t)(m + 8) * DM + n];
                v1.y += bias[n + 1] + resid[(size_t)(m + 8) * DM + n + 1];
                *(float2*)&C[(size_t)m * DM + n]       = v0;
                *(float2*)&C[(size_t)(m + 8) * DM + n] = v1;
            }
        }
    }
}

// ---------------------------------------------------------------------------
// Fused scores + softmax. CTA = 32 q-rows x full 1024 j for one (h,b).
// HMMA with Q/K bf16 hi/lo (3-MMA split). Scores in registers, softmax via
// shfl + smem cross-warp reduce, single fp32 write of attns.
// Warp w covers j in [w*128, w*128+128). acc[2][16][4] = 128 regs.
// ---------------------------------------------------------------------------
#define SC_QROW 144
#define SC_KROW 48
#define SC_QSZ  (32 * SC_QROW)            // 4608 per component
#define SC_K_OFF (2 * SC_QSZ)             // 9216
#define SC_KCSZ (1024 * SC_KROW)          // 49152 per component
#define SC_KBUF (2 * SC_KCSZ)             // 98304 per buffer
#define SC_SMEM (SC_K_OFF + 2 * SC_KBUF)  // 205824

__global__ __launch_bounds__(256, 1) void scores_softmax(
    const bf16* __restrict__ Qh, const bf16* __restrict__ Ql,
    const bf16* __restrict__ Kh, const bf16* __restrict__ Kl,
    const unsigned char* __restrict__ mask, float* __restrict__ attns)
{
    extern __shared__ __align__(128) char smem[];
    const uint32_t sb = smem_u32(smem);
    __shared__ float red[8][32];
    const int tid = threadIdx.x;
    const int w = tid >> 5;
    const int lane = tid & 31;
    const int hb = blockIdx.y;
    const int h = hb >> 3;
    const int b = hb & 7;
    const int i0 = blockIdx.x * 32;
    const int base = b * LQ;
    const int hc = h * DK;

    // Stage Q (32 rows x 64 d, hi+lo) into smem
    #pragma unroll
    for (int i = 0; i < 2; i++) {
        int t = tid + i * 256;
        int comp = t >> 8;
        int r = (t >> 3) & 31;
        int u = t & 7;
        const bf16* src = comp ? Ql : Qh;
        uint4 val = *(const uint4*)&src[(size_t)(base + i0 + r) * DM + hc + u * 8];
        *(uint4*)(smem + comp * SC_QSZ + r * SC_QROW + u * 16) = val;
    }

    auto load_k = [&](int ks, uint32_t boff) {
        const int d0 = hc + ks * 16;
        #pragma unroll
        for (int i = 0; i < 16; i++) {
            int t = i * 256 + tid;           // 0..4095
            int comp = t >> 11;
            int j = (t >> 1) & 1023;
            int u = t & 1;
            const bf16* src = comp ? Kl : Kh;
            cpasync16(sb + boff + comp * SC_KCSZ + (uint32_t)(j * SC_KROW + u * 16),
                      src + (size_t)(base + j) * DM + d0 + u * 8);
        }
    };

    float acc[2][16][4];
    #pragma unroll
    for (int mt = 0; mt < 2; mt++)
        #pragma unroll
        for (int nt = 0; nt < 16; nt++)
            #pragma unroll
            for (int e = 0; e < 4; e++) acc[mt][nt][e] = 0.f;

    load_k(0, SC_K_OFF);
    cpasync_commit();

    for (int ks = 0; ks < 4; ks++) {
        cpasync_wait0();
        __syncthreads();
        const uint32_t kb = sb + SC_K_OFF + (uint32_t)((ks & 1) * SC_KBUF);
        if (ks < 3) {
            load_k(ks + 1, SC_K_OFF + (uint32_t)(((ks + 1) & 1) * SC_KBUF));
            cpasync_commit();
        } else {
            cpasync_commit();
        }

        uint32_t ah[2][4], al[2][4];
        #pragma unroll
        for (int mt = 0; mt < 2; mt++) {
            uint32_t ao = sb + (uint32_t)((mt * 16 + (lane & 15)) * SC_QROW
                                          + ((lane >> 4) & 1) * 16 + ks * 32);
            ldsm4(ah[mt], ao);
            ldsm4(al[mt], ao + SC_QSZ);
        }
        #pragma unroll
        for (int nt2 = 0; nt2 < 8; nt2++) {
            uint32_t bo = kb + (uint32_t)((w * 128 + nt2 * 16 + (lane & 15)) * SC_KROW
                                          + ((lane >> 4) & 1) * 16);
            uint32_t bh[4], bl[4];
            ldsm4(bh, bo);
            ldsm4(bl, bo + SC_KCSZ);
            #pragma unroll
            for (int mt = 0; mt < 2; mt++) {
                #pragma unroll
                for (int s = 0; s < 2; s++) {
                    float* d = acc[mt][nt2 * 2 + s];
                    mma16816(d, ah[mt], bh[s], bh[2 + s]);
                    mma16816(d, ah[mt], bl[s], bl[2 + s]);
                    mma16816(d, al[mt], bh[s], bh[2 + s]);
                }
            }
        }
        __syncthreads();
    }

    // ---- scale + mask (in place) ----
    const float scale = 0.03125f;           // 1/sqrt(1024)
    #pragma unroll
    for (int g = 0; g < 4; g++) {
        const int mt = g >> 1, eh = g & 1;
        const int rr = mt * 16 + (lane >> 2) + eh * 8;
        const unsigned char* mrow = mask + ((size_t)b * LQ + i0 + rr) * LQ
                                    + w * 128 + (lane & 3) * 2;
        #pragma unroll
        for (int nt = 0; nt < 16; nt++) {
            uchar2 mv = *(const uchar2*)(mrow + nt * 8);
            float* pa = &acc[mt][nt][eh * 2];
            pa[0] = mv.x ? -1e30f : pa[0] * scale;
            pa[1] = mv.y ? -1e30f : pa[1] * scale;
        }
    }

    // ---- row max ----
    float mrow_[4];
    #pragma unroll
    for (int g = 0; g < 4; g++) {
        const int mt = g >> 1, eh = g & 1;
        float mm = -1e30f;
        #pragma unroll
        for (int nt = 0; nt < 16; nt++) {
            mm = fmaxf(mm, fmaxf(acc[mt][nt][eh * 2], acc[mt][nt][eh * 2 + 1]));
        }
        mm = fmaxf(mm, __shfl_xor_sync(0xffffffffu, mm, 1));
        mm = fmaxf(mm, __shfl_xor_sync(0xffffffffu, mm, 2));
        mrow_[g] = mm;
    }
    if ((lane & 3) == 0) {
        #pragma unroll
        for (int g = 0; g < 4; g++) {
            const int rr = (g >> 1) * 16 + (lane >> 2) + (g & 1) * 8;
            red[w][rr] = mrow_[g];
        }
    }
    __syncthreads();
    #pragma unroll
    for (int g = 0; g < 4; g++) {
        const int rr = (g >> 1) * 16 + (lane >> 2) + (g & 1) * 8;
        float mm = red[0][rr];
        #pragma unroll
        for (int ww = 1; ww < 8; ww++) mm = fmaxf(mm, red[ww][rr]);
        mrow_[g] = mm;
    }
    __syncthreads();

    // ---- exp + row sum ----
    float srow_[4];
    #pragma unroll
    for (int g = 0; g < 4; g++) {
        const int mt = g >> 1, eh = g & 1;
        float ss = 0.f;
        #pragma unroll
        for (int nt = 0; nt < 16; nt++) {
            float* pa = &acc[mt][nt][eh * 2];
            pa[0] = fexp(pa[0] - mrow_[g]);
            pa[1] = fexp(pa[1] - mrow_[g]);
            ss += pa[0] + pa[1];
        }
        ss += __shfl_xor_sync(0xffffffffu, ss, 1);
        ss += __shfl_xor_sync(0xffffffffu, ss, 2);
        srow_[g] = ss;
    }
    if ((lane & 3) == 0) {
        #pragma unroll
        for (int g = 0; g < 4; g++) {
            const int rr = (g >> 1) * 16 + (lane >> 2) + (g & 1) * 8;
            red[w][rr] = srow_[g];
        }
    }
    __syncthreads();
    #pragma unroll
    for (int g = 0; g < 4; g++) {
        const int rr = (g >> 1) * 16 + (lane >> 2) + (g & 1) * 8;
        float ss = 0.f;
        #pragma unroll
        for (int ww = 0; ww < 8; ww++) ss += red[ww][rr];
        srow_[g] = 1.0f / ss;
    }

    // ---- normalized write ----
    #pragma unroll
    for (int g = 0; g < 4; g++) {
        const int mt = g >> 1, eh = g & 1;
        const int rr = mt * 16 + (lane >> 2) + eh * 8;
        float* orow = attns + ((size_t)hb * LQ + i0 + rr) * LQ
                      + w * 128 + (lane & 3) * 2;
        const float inv = srow_[g];
        #pragma unroll
        for (int nt = 0; nt < 16; nt++) {
            float2 o = make_float2(acc[mt][nt][eh * 2] * inv,
                                   acc[mt][nt][eh * 2 + 1] * inv);
            *(float2*)(orow + nt * 8) = o;
        }
    }
}

// ---------------------------------------------------------------------------
// AV HMMA: Oh[b,i,hc+v] = sum_j attn[hb,i,j] * V[b,j,hc+v]
// CTA = 128 i x 64 v, j chunks of 32. attn fp32 -> bf16(hi) in smem;
// V hi/lo via ldmatrix.trans. Emits oh hi/lo for the proj GEMM.
// ---------------------------------------------------------------------------
#define AV_AROW 80
#define AV_ASZ  (128 * AV_AROW)          // 10240
#define AV_VROW 144
#define AV_VSZ  (32 * AV_VROW)           // 4608 per component
#define AV_V_OFF AV_ASZ
#define AV_SMEM (AV_ASZ + 2 * AV_VSZ)    // 19456

__global__ __launch_bounds__(256) void av_hmma(
    const float* __restrict__ attns,
    const bf16* __restrict__ Vh, const bf16* __restrict__ Vl,
    bf16* __restrict__ Oh, bf16* __restrict__ Ol)
{
    extern __shared__ __align__(128) char smem[];
    const uint32_t sb = smem_u32(smem);
    const int tid = threadIdx.x;
    const int wid = tid >> 5;
    const int lane = tid & 31;
    const int i0 = blockIdx.x * 128;
    const int hb = blockIdx.y;
    const int h = hb >> 3;
    const int b = hb & 7;
    const int base = b * LQ;
    const int hc = h * DK;
    const int wm = wid >> 1;
    const int wn = wid & 1;
    const float* arow = attns + ((size_t)hb * LQ + i0) * LQ;

    float acc[2][4][4];
    #pragma unroll
    for (int mt = 0; mt < 2; mt++)
        #pragma unroll
        for (int nt = 0; nt < 4; nt++)
            #pragma unroll
            for (int e = 0; e < 4; e++) acc[mt][nt][e] = 0.f;

    for (int j0 = 0; j0 < LQ; j0 += 32) {
        __syncthreads();    // previous MMAs done reading smem
        // attn load + convert to bf16 hi
        #pragma unroll
        for (int i = 0; i < 4; i++) {
            int t = i * 256 + tid;       // 0..1023
            int r = t >> 3;
            int u = t & 7;
            float4 v = *(const float4*)&arow[(size_t)r * LQ + j0 + u * 4];
            uint2 pk;
            pk.x = bf2_as_u32(__floats2bfloat162_rn(v.x, v.y));
            pk.y = bf2_as_u32(__floats2bfloat162_rn(v.z, v.w));
            *(uint2*)(smem + r * AV_AROW + u * 8) = pk;
        }
        // V hi/lo via cp.async: 512 tasks = 2 comps x 32 rows x 8 16B-units
        #pragma unroll
        for (int t2 = 0; t2 < 2; t2++) {
            int t = t2 * 256 + tid;      // 0..511
            int comp = t >> 8;
            int r = (t >> 3) & 31;
            int u = t & 7;
            const bf16* src = comp ? Vl : Vh;
            cpasync16(sb + AV_V_OFF + comp * AV_VSZ + (uint32_t)(r * AV_VROW + u * 16),
                      src + (size_t)(base + j0 + r) * DM + hc + u * 8);
        }
        cpasync_commit();
        cpasync_wait0();
        __syncthreads();

        #pragma unroll
        for (int ks = 0; ks < 2; ks++) {
            uint32_t a[2][4];
            #pragma unroll
            for (int mt = 0; mt < 2; mt++) {
                uint32_t ao = sb + (uint32_t)((wm * 32 + mt * 16 + (lane & 15)) * AV_AROW
                                              + ((lane >> 4) & 1) * 16 + ks * 32);
                ldsm4(a[mt], ao);
            }
            #pragma unroll
            for (int nt2 = 0; nt2 < 2; nt2++) {
                // trans-load: B fragment (col-major n8k16) from V rows=j, cols=v
                uint32_t vrow = (uint32_t)(ks * 16 + (lane & 7) + ((lane >> 4) << 3));
                uint32_t vcol = (uint32_t)((wn * 32 + nt2 * 16) * 2 + (((lane >> 3) & 1) << 4));
                uint32_t vo = sb + AV_V_OFF + vrow * AV_VROW + vcol;
                uint32_t vh[4], vl[4];
                ldsm4t(vh, vo);
                ldsm4t(vl, vo + AV_VSZ);
                #pragma unroll
                for (int mt = 0; mt < 2; mt++) {
                    #pragma unroll
                    for (int s = 0; s < 2; s++) {
                        float* d = acc[mt][nt2 * 2 + s];
                        mma16816(d, a[mt], vh[s], vh[2 + s]);
                        mma16816(d, a[mt], vl[s], vl[2 + s]);
                    }
                }
            }
        }
    }

    const int erow = i0 + wm * 32 + (lane >> 2);
    const int ecol = hc + wn * 32 + (lane & 3) * 2;
    #pragma unroll
    for (int mt = 0; mt < 2; mt++) {
        #pragma unroll
        for (int nt = 0; nt < 4; nt++) {
            #pragma unroll
            for (int half = 0; half < 2; half++) {
                int m = erow + mt * 16 + half * 8;
                int n = ecol + nt * 8;
                size_t off = ((size_t)b * LQ + m) * DM + n;
                float a0 = acc[mt][nt][half * 2 + 0];
                float a1 = acc[mt][nt][half * 2 + 1];
                float h0 = __bfloat162float(__float2bfloat16_rn(a0));
                float h1 = __bfloat162float(__float2bfloat16_rn(a1));
                *(__nv_bfloat162*)&Oh[off] = __floats2bfloat162_rn(h0, h1);
                *(__nv_bfloat162*)&Ol[off] = __floats2bfloat162_rn(a0 - h0, a1 - h1);
            }
        }
    }
}

// ---------------------------------------------------------------------------
// LayerNorm: one block per row of 1024.
// ---------------------------------------------------------------------------
__global__ __launch_bounds__(256) void ln_kernel(const float* __restrict__ X,
                                                 const float* __restrict__ gamma,
                                                 const float* __restrict__ beta,
                                                 float* __restrict__ out)
{
    __shared__ float sred[32];
    const float* p = X + (size_t)blockIdx.x * DM;
    const int tid = threadIdx.x;

    float4 v = *(const float4*)&p[tid * 4];
    float s  = v.x + v.y + v.z + v.w;
    float sq = v.x * v.x + v.y * v.y + v.z * v.z + v.w * v.w;
    #pragma unroll
    for (int o = 16; o; o >>= 1) {
        s  += __shfl_xor_sync(0xffffffffu, s,  o);
        sq += __shfl_xor_sync(0xffffffffu, sq, o);
    }
    if ((tid & 31) == 0) { sred[tid >> 5] = s; sred[8 + (tid >> 5)] = sq; }
    __syncthreads();
    if (tid == 0) {
        float ts = 0.f, tq = 0.f;
        #pragma unroll
        for (int i = 0; i < 8; i++) { ts += sred[i]; tq += sred[8 + i]; }
        sred[16] = ts; sred[17] = tq;
    }
    __syncthreads();
    const float mean = sred[16] * (1.0f / DM);
    const float var  = sred[17] * (1.0f / DM) - mean * mean;
    const float inv  = rsqrtf(var + 1e-5f);

    float4 g  = *(const float4*)&gamma[tid * 4];
    float4 bb = *(const float4*)&beta[tid * 4];
    float4 o4;
    o4.x = (v.x - mean) * inv * g.x + bb.x;
    o4.y = (v.y - mean) * inv * g.y + bb.y;
    o4.z = (v.z - mean) * inv * g.z + bb.z;
    o4.w = (v.w - mean) * inv * g.w + bb.w;
    *(float4*)&out[(size_t)blockIdx.x * DM + tid * 4] = o4;
}

// ---------------------------------------------------------------------------
extern "C" void kernel_launch(void* const* d_in, const int* in_sizes, int n_in,
                              void* d_out, int out_size)
{
    const float* q       = (const float*)d_in[0];
    const float* k       = (const float*)d_in[1];
    const float* v       = (const float*)d_in[2];
    const unsigned char* mask = (const unsigned char*)d_in[3];
    const float* w_qs    = (const float*)d_in[4];
    const float* w_ks    = (const float*)d_in[5];
    const float* w_vs    = (const float*)d_in[6];
    const float* proj_w  = (const float*)d_in[7];
    const float* proj_b  = (const float*)d_in[8];
    const float* ln_g    = (const float*)d_in[9];
    const float* ln_b    = (const float*)d_in[10];

    float* out   = (float*)d_out;
    float* attns = out + OUT_ELEMS;

    #define SYM(T, name) T* name; { void* p_; cudaGetSymbolAddress(&p_, g_##name); name = (T*)p_; }
    SYM(bf16, q_h)  SYM(bf16, q_l)
    SYM(bf16, k_h)  SYM(bf16, k_l)
    SYM(bf16, v_h)  SYM(bf16, v_l)
    SYM(bf16, wq_h) SYM(bf16, wq_l)
    SYM(bf16, wk_h) SYM(bf16, wk_l)
    SYM(bf16, wv_h) SYM(bf16, wv_l)
    SYM(bf16, wp_h) SYM(bf16, wp_l)
    SYM(bf16, pq_h) SYM(bf16, pq_l)
    SYM(bf16, pk_h) SYM(bf16, pk_l)
    SYM(bf16, pv_h) SYM(bf16, pv_l)
    SYM(bf16, oh_h) SYM(bf16, oh_l)
    SYM(float, x)
    #undef SYM

    cudaFuncSetAttribute(gemm_bf16x2<0>, cudaFuncAttributeMaxDynamicSharedMemorySize, GEMM_SMEM);
    cudaFuncSetAttribute(gemm_bf16x2<1>, cudaFuncAttributeMaxDynamicSharedMemorySize, GEMM_SMEM);
    cudaFuncSetAttribute(scores_softmax, cudaFuncAttributeMaxDynamicSharedMemorySize, SC_SMEM);
    cudaFuncSetAttribute(av_hmma, cudaFuncAttributeMaxDynamicSharedMemorySize, AV_SMEM);

    // 1. split inputs and weights to bf16 hi/lo
    const int n4_in = BL * DM / 4;
    split_fp32<<<n4_in / 256, 256>>>(q, q_h, q_l, n4_in);
    split_fp32<<<n4_in / 256, 256>>>(k, k_h, k_l, n4_in);
    split_fp32<<<n4_in / 256, 256>>>(v, v_h, v_l, n4_in);
    const int n4_w = DM * DM / 4;
    split_fp32<<<n4_w / 256, 256>>>(proj_w, wp_h, wp_l, n4_w);
    wqkv_split<<<DM * DM / 256, 256>>>(w_qs, wq_h, wq_l);
    wqkv_split<<<DM * DM / 256, 256>>>(w_ks, wk_h, wk_l);
    wqkv_split<<<DM * DM / 256, 256>>>(w_vs, wv_h, wv_l);

    // 2. QKV projections (HMMA, bf16 hi/lo outputs)
    dim3 gg(DM / 64, BL / 128);
    gemm_bf16x2<1><<<gg, 256, GEMM_SMEM>>>(q_h, q_l, wq_h, wq_l, nullptr, pq_h, pq_l, nullptr, nullptr);
    gemm_bf16x2<1><<<gg, 256, GEMM_SMEM>>>(k_h, k_l, wk_h, wk_l, nullptr, pk_h, pk_l, nullptr, nullptr);
    gemm_bf16x2<1><<<gg, 256, GEMM_SMEM>>>(v_h, v_l, wv_h, wv_l, nullptr, pv_h, pv_l, nullptr, nullptr);

    // 3. fused scores + softmax (single attns write), then AV (HMMA)
    scores_softmax<<<dim3(32, 128), 256, SC_SMEM>>>(pq_h, pq_l, pk_h, pk_l, mask, attns);
    av_hmma<<<dim3(8, 128), 256, AV_SMEM>>>(attns, pv_h, pv_l, oh_h, oh_l);

    // 4. output projection (HMMA, fused bias + residual) and LN
    gemm_bf16x2<0><<<gg, 256, GEMM_SMEM>>>(oh_h, oh_l, wp_h, wp_l, x, nullptr, nullptr, proj_b, q);
    ln_kernel<<<BL, 256>>>(x, ln_g, ln_b, out);
}